// round 3
// baseline (speedup 1.0000x reference)
#include <cuda_runtime.h>
#include <cuda_bf16.h>

// Shapes: B=32, S=2048, I=128, A=128, H=256, K=8, ACTIVE=3 (structurally k=0,1,2)
#define NB 32
#define NS 2048
#define NI 128
#define NA 128
#define NH 256
#define NK 8
#define KACT 3
#define CHUNKS 16
#define ROWS_PER_BLOCK (NS / CHUNKS)       // 128
#define ROWS_PER_WARP (ROWS_PER_BLOCK / 8) // 16

// Device scratch (allocation-free rule: __device__ globals)
__device__ float g_qpart[KACT][8][NA];           // partial q over h-chunks
__device__ float g_u[KACT][NI];                  // u[k] = W_k[k] @ q[k]
__device__ float g_hpre[KACT][NH];               // rim[k] @ W_hh + b
__device__ float g_ypart[NB][CHUNKS][KACT * NI]; // per-chunk partial y

// ---------------------------------------------------------------------------
// Prologue 1: everything that has no dependency — one DRAM-latency batch each.
//   blocks 0..23  : (k, p)   q-partials: q_p[k][a] = sum_{h in chunk p} rim*Wq
//   blocks 24..35 : (k, hq)  hpre[k][h] with 8-way split reduction
// ---------------------------------------------------------------------------
__global__ __launch_bounds__(512) void prologue1_kernel(
    const float* __restrict__ rim, const float* __restrict__ Wq,
    const float* __restrict__ Whh, const float* __restrict__ bias)
{
    const int tid = threadIdx.x;
    const int bid = blockIdx.x;

    if (bid < KACT * 8) {
        // ---- q partial: block (k, p) covers h in [p*32, p*32+32)
        const int k = bid >> 3;
        const int p = bid & 7;
        const int a   = tid & 127;
        const int sub = tid >> 7;              // 0..3, 8 h's each
        const int h0  = p * 32 + sub * 8;
        const float* __restrict__ wq = Wq + ((size_t)(k * NH + h0)) * NA + a;
        const float* __restrict__ rk = rim + k * NH + h0;

        float acc0 = rk[0] * wq[0 * NA];
        float acc1 = rk[1] * wq[1 * NA];
        float acc2 = rk[2] * wq[2 * NA];
        float acc3 = rk[3] * wq[3 * NA];
        acc0 += rk[4] * wq[4 * NA];
        acc1 += rk[5] * wq[5 * NA];
        acc2 += rk[6] * wq[6 * NA];
        acc3 += rk[7] * wq[7 * NA];

        __shared__ float qp[4][NA];
        qp[sub][a] = (acc0 + acc1) + (acc2 + acc3);
        __syncthreads();
        if (tid < NA)
            g_qpart[k][p][tid] = (qp[0][tid] + qp[1][tid]) + (qp[2][tid] + qp[3][tid]);
    } else {
        // ---- hpre: block (k, hq) covers h in [hq*64, hq*64+64)
        const int idx = bid - KACT * 8;
        const int k  = idx >> 2;
        const int hq = idx & 3;
        const int h  = hq * 64 + (tid & 63);
        const int part = tid >> 6;             // 0..7, hp range [part*32, part*32+32)
        const float* __restrict__ rk = rim + k * NH + part * 32;
        const float* __restrict__ wh = Whh + (size_t)(part * 32) * NH + h;

        float acc0 = 0.f, acc1 = 0.f, acc2 = 0.f, acc3 = 0.f;
        #pragma unroll
        for (int hp = 0; hp < 32; hp += 4) {
            acc0 += rk[hp + 0] * wh[(size_t)(hp + 0) * NH];
            acc1 += rk[hp + 1] * wh[(size_t)(hp + 1) * NH];
            acc2 += rk[hp + 2] * wh[(size_t)(hp + 2) * NH];
            acc3 += rk[hp + 3] * wh[(size_t)(hp + 3) * NH];
        }
        __shared__ float hp_s[8][64];
        hp_s[part][tid & 63] = (acc0 + acc1) + (acc2 + acc3);
        __syncthreads();
        if (tid < 64) {
            float s = ((hp_s[0][tid] + hp_s[1][tid]) + (hp_s[2][tid] + hp_s[3][tid]))
                    + ((hp_s[4][tid] + hp_s[5][tid]) + (hp_s[6][tid] + hp_s[7][tid]));
            g_hpre[k][h] = bias[h] + s;
        }
    }
}

// ---------------------------------------------------------------------------
// Prologue 2: combine q partials (L2-resident) then u[k][i] = Wk[k][i][:].q
// One block per k. u-stage: one float4 per lane covers a whole 512B row.
// ---------------------------------------------------------------------------
__global__ __launch_bounds__(256) void prologue2_kernel(const float* __restrict__ Wk)
{
    const int k = blockIdx.x;
    const int tid = threadIdx.x;
    __shared__ float qh[2][NA];
    __shared__ float qs[NA];

    {
        const int a = tid & 127;
        const int half = tid >> 7;             // sums parts [half*4, half*4+4)
        const float* qp = &g_qpart[k][half * 4][0];
        qh[half][a] = (qp[0 * NA + a] + qp[1 * NA + a])
                    + (qp[2 * NA + a] + qp[3 * NA + a]);
    }
    __syncthreads();
    if (tid < NA) qs[tid] = qh[0][tid] + qh[1][tid];
    __syncthreads();

    const int warp = tid >> 5, lane = tid & 31;
    const float4 q4 = reinterpret_cast<const float4*>(qs)[lane];
    const float4* __restrict__ wkbase =
        reinterpret_cast<const float4*>(Wk + ((size_t)k * NI) * NA);
    #pragma unroll
    for (int ii = 0; ii < 16; ++ii) {
        const int i = warp * 16 + ii;
        const float4 w4 = wkbase[(size_t)i * 32 + lane];
        float p = w4.x * q4.x + w4.y * q4.y + w4.z * q4.z + w4.w * q4.w;
        #pragma unroll
        for (int off = 16; off; off >>= 1) p += __shfl_xor_sync(0xffffffffu, p, off);
        if (lane == 0) g_u[k][i] = p;
    }
}

// ---------------------------------------------------------------------------
// Main: y[b][k][i] = sum_s x[b][s][i] * (x[b][s] . u[k]),  k = 0..2
// ---------------------------------------------------------------------------
__global__ __launch_bounds__(256) void main_kernel(const float* __restrict__ x)
{
    const int b     = blockIdx.x >> 4;
    const int chunk = blockIdx.x & 15;
    const int warp  = threadIdx.x >> 5;
    const int lane  = threadIdx.x & 31;

    const size_t row0 = (size_t)b * NS + chunk * ROWS_PER_BLOCK + warp * ROWS_PER_WARP;
    const float4* xr = reinterpret_cast<const float4*>(x + row0 * NI) + lane;

    const float4 u0 = reinterpret_cast<const float4*>(g_u[0])[lane];
    const float4 u1 = reinterpret_cast<const float4*>(g_u[1])[lane];
    const float4 u2 = reinterpret_cast<const float4*>(g_u[2])[lane];

    float4 a0 = make_float4(0.f, 0.f, 0.f, 0.f);
    float4 a1 = a0, a2 = a0;

    #pragma unroll 4
    for (int r = 0; r < ROWS_PER_WARP; ++r) {
        const float4 xv = xr[r * 32];
        float d0 = xv.x * u0.x + xv.y * u0.y + xv.z * u0.z + xv.w * u0.w;
        float d1 = xv.x * u1.x + xv.y * u1.y + xv.z * u1.z + xv.w * u1.w;
        float d2 = xv.x * u2.x + xv.y * u2.y + xv.z * u2.z + xv.w * u2.w;
        #pragma unroll
        for (int off = 16; off; off >>= 1) {
            d0 += __shfl_xor_sync(0xffffffffu, d0, off);
            d1 += __shfl_xor_sync(0xffffffffu, d1, off);
            d2 += __shfl_xor_sync(0xffffffffu, d2, off);
        }
        a0.x += d0 * xv.x; a0.y += d0 * xv.y; a0.z += d0 * xv.z; a0.w += d0 * xv.w;
        a1.x += d1 * xv.x; a1.y += d1 * xv.y; a1.z += d1 * xv.z; a1.w += d1 * xv.w;
        a2.x += d2 * xv.x; a2.y += d2 * xv.y; a2.z += d2 * xv.z; a2.w += d2 * xv.w;
    }

    __shared__ float ysw[8][KACT * NI];
    reinterpret_cast<float4*>(&ysw[warp][0 * NI])[lane] = a0;
    reinterpret_cast<float4*>(&ysw[warp][1 * NI])[lane] = a1;
    reinterpret_cast<float4*>(&ysw[warp][2 * NI])[lane] = a2;
    __syncthreads();

    float* yp = g_ypart[b][chunk];
    for (int idx = threadIdx.x; idx < KACT * NI; idx += 256) {
        float s = 0.f;
        #pragma unroll
        for (int w = 0; w < 8; ++w) s += ysw[w][idx];
        yp[idx] = s;
    }
}

// ---------------------------------------------------------------------------
// Epilogue: per batch b (384 threads) —
//   y = sum over chunks;  att[k] = W_v[k]^T y[k];
//   out[b][k] = tanh(att[k] @ W_ih + hpre[k])  for k<3, else rim[k]
// ---------------------------------------------------------------------------
__global__ __launch_bounds__(384) void epilogue_kernel(
    const float* __restrict__ rim, const float* __restrict__ Wv,
    const float* __restrict__ Wih, float* __restrict__ out)
{
    const int b = blockIdx.x;
    const int tid = threadIdx.x;
    __shared__ float ys[KACT * NI];
    __shared__ float att[KACT * NA];

    // reduce partials (L2-resident, deterministic order): 384 items, 1/thread
    {
        const float* yp = &g_ypart[b][0][0];
        float s0 = 0.f, s1 = 0.f, s2 = 0.f, s3 = 0.f;
        #pragma unroll
        for (int c = 0; c < CHUNKS; c += 4) {
            s0 += yp[(c + 0) * (KACT * NI) + tid];
            s1 += yp[(c + 1) * (KACT * NI) + tid];
            s2 += yp[(c + 2) * (KACT * NI) + tid];
            s3 += yp[(c + 3) * (KACT * NI) + tid];
        }
        ys[tid] = (s0 + s1) + (s2 + s3);
    }
    __syncthreads();

    // attended[k][a] = sum_i Wv[k][i][a] * ys[k][i]   (384 outputs, 1/thread)
    {
        const int k = tid >> 7, a = tid & 127;
        const float* __restrict__ wv = Wv + (size_t)k * NI * NA + a;
        const float* __restrict__ yk = ys + k * NI;
        float acc0 = 0.f, acc1 = 0.f, acc2 = 0.f, acc3 = 0.f;
        #pragma unroll
        for (int i = 0; i < NI; i += 8) {
            acc0 += wv[(size_t)(i + 0) * NA] * yk[i + 0];
            acc1 += wv[(size_t)(i + 1) * NA] * yk[i + 1];
            acc2 += wv[(size_t)(i + 2) * NA] * yk[i + 2];
            acc3 += wv[(size_t)(i + 3) * NA] * yk[i + 3];
            acc0 += wv[(size_t)(i + 4) * NA] * yk[i + 4];
            acc1 += wv[(size_t)(i + 5) * NA] * yk[i + 5];
            acc2 += wv[(size_t)(i + 6) * NA] * yk[i + 6];
            acc3 += wv[(size_t)(i + 7) * NA] * yk[i + 7];
        }
        att[tid] = (acc0 + acc1) + (acc2 + acc3);
    }
    __syncthreads();

    float* ob = out + (size_t)b * NK * NH;

    // cand for k = 0..2 (768 outputs, 2/thread)
    for (int j = tid; j < KACT * NH; j += 384) {
        const int k = j >> 8, h = j & 255;
        const float* __restrict__ ak = att + k * NA;
        float acc0 = g_hpre[k][h], acc1 = 0.f, acc2 = 0.f, acc3 = 0.f;
        #pragma unroll
        for (int a = 0; a < NA; a += 8) {
            acc0 += ak[a + 0] * Wih[(size_t)(a + 0) * NH + h];
            acc1 += ak[a + 1] * Wih[(size_t)(a + 1) * NH + h];
            acc2 += ak[a + 2] * Wih[(size_t)(a + 2) * NH + h];
            acc3 += ak[a + 3] * Wih[(size_t)(a + 3) * NH + h];
            acc0 += ak[a + 4] * Wih[(size_t)(a + 4) * NH + h];
            acc1 += ak[a + 5] * Wih[(size_t)(a + 5) * NH + h];
            acc2 += ak[a + 6] * Wih[(size_t)(a + 6) * NH + h];
            acc3 += ak[a + 7] * Wih[(size_t)(a + 7) * NH + h];
        }
        ob[j] = tanhf((acc0 + acc1) + (acc2 + acc3));
    }
    // k = 3..7: passthrough rim_hidden
    for (int j = tid; j < (NK - KACT) * NH; j += 384) {
        ob[KACT * NH + j] = rim[KACT * NH + j];
    }
}

// ---------------------------------------------------------------------------
extern "C" void kernel_launch(void* const* d_in, const int* in_sizes, int n_in,
                              void* d_out, int out_size)
{
    const float* x    = (const float*)d_in[0];
    const float* rim  = (const float*)d_in[1];
    const float* Wq   = (const float*)d_in[2];
    const float* Wk   = (const float*)d_in[3];
    const float* Wv   = (const float*)d_in[4];
    const float* Wih  = (const float*)d_in[5];
    const float* Whh  = (const float*)d_in[6];
    const float* bias = (const float*)d_in[7];
    float* out = (float*)d_out;

    prologue1_kernel<<<KACT * 8 + KACT * 4, 512>>>(rim, Wq, Whh, bias);
    prologue2_kernel<<<KACT, 256>>>(Wk);
    main_kernel<<<NB * CHUNKS, 256>>>(x);
    epilogue_kernel<<<NB, 384>>>(rim, Wv, Wih, out);
}

// round 4
// speedup vs baseline: 1.1759x; 1.1759x over previous
#include <cuda_runtime.h>
#include <cuda_bf16.h>

// Shapes: B=32, S=2048, I=128, A=128, H=256, K=8, ACTIVE=3 (structurally k=0,1,2)
#define NB 32
#define NS 2048
#define NI 128
#define NA 128
#define NH 256
#define NK 8
#define KACT 3
#define CHUNKS 16
#define ROWS_PER_BLOCK (NS / CHUNKS)       // 128
#define ROWS_PER_WARP (ROWS_PER_BLOCK / 8) // 16

// Device scratch (allocation-free rule: __device__ globals)
__device__ float g_u[KACT][NI];                  // u[k] = W_k[k] @ q[k]
__device__ float g_hpre[KACT][NH];               // rim[k] @ W_hh + b
__device__ float g_ypart[NB][CHUNKS][KACT * NI]; // per-chunk partial y

// ---------------------------------------------------------------------------
// Prologue (one kernel, 9 blocks x 1024 threads, ~1 latency batch per stage):
//   blocks 0..2 : k-block. q[k][a] = sum_h rim*Wq  (128a x 8 parts x 32 loads)
//                 then u[k][i] = Wk[k][i][:].q     (4 rows per warp)
//   blocks 3..8 : (k, h-half) hpre  (128h x 8 parts x 32 loads)
// ---------------------------------------------------------------------------
__global__ __launch_bounds__(1024) void prologue_kernel(
    const float* __restrict__ rim, const float* __restrict__ Wq,
    const float* __restrict__ Wk, const float* __restrict__ Whh,
    const float* __restrict__ bias)
{
    const int tid = threadIdx.x;
    const int bid = blockIdx.x;

    if (bid < KACT) {
        const int k = bid;
        __shared__ float qp[8][NA];
        __shared__ __align__(16) float qs[NA];

        // ---- stage 1: q partials, 32 fully-unrolled independent loads/thread
        {
            const int a    = tid & 127;
            const int part = tid >> 7;           // 0..7
            const int h0   = part * 32;
            const float* __restrict__ wq = Wq + ((size_t)(k * NH + h0)) * NA + a;
            const float* __restrict__ rk = rim + k * NH + h0;
            float acc0 = 0.f, acc1 = 0.f, acc2 = 0.f, acc3 = 0.f;
            #pragma unroll
            for (int h = 0; h < 32; h += 4) {
                acc0 += rk[h + 0] * wq[(size_t)(h + 0) * NA];
                acc1 += rk[h + 1] * wq[(size_t)(h + 1) * NA];
                acc2 += rk[h + 2] * wq[(size_t)(h + 2) * NA];
                acc3 += rk[h + 3] * wq[(size_t)(h + 3) * NA];
            }
            qp[part][a] = (acc0 + acc1) + (acc2 + acc3);
        }
        __syncthreads();
        if (tid < NA) {
            qs[tid] = ((qp[0][tid] + qp[1][tid]) + (qp[2][tid] + qp[3][tid]))
                    + ((qp[4][tid] + qp[5][tid]) + (qp[6][tid] + qp[7][tid]));
        }
        __syncthreads();

        // ---- stage 2: u[k][i]; 32 warps x 4 rows, one float4/lane per row
        const int warp = tid >> 5, lane = tid & 31;
        const float4 q4 = reinterpret_cast<const float4*>(qs)[lane];
        const float4* __restrict__ wkbase =
            reinterpret_cast<const float4*>(Wk + ((size_t)k * NI) * NA);
        #pragma unroll
        for (int ii = 0; ii < 4; ++ii) {
            const int i = warp * 4 + ii;
            const float4 w4 = wkbase[(size_t)i * 32 + lane];
            float p = w4.x * q4.x + w4.y * q4.y + w4.z * q4.z + w4.w * q4.w;
            #pragma unroll
            for (int off = 16; off; off >>= 1) p += __shfl_xor_sync(0xffffffffu, p, off);
            if (lane == 0) g_u[k][i] = p;
        }
    } else {
        // ---- hpre: block (k, half). 128h x 8 parts x 32 loads = 1 batch
        const int idx  = bid - KACT;
        const int k    = idx >> 1;
        const int half = idx & 1;
        const int h    = half * 128 + (tid & 127);
        const int part = tid >> 7;               // 0..7
        const float* __restrict__ rk = rim + k * NH + part * 32;
        const float* __restrict__ wh = Whh + (size_t)(part * 32) * NH + h;

        float acc0 = 0.f, acc1 = 0.f, acc2 = 0.f, acc3 = 0.f;
        #pragma unroll
        for (int hp = 0; hp < 32; hp += 4) {
            acc0 += rk[hp + 0] * wh[(size_t)(hp + 0) * NH];
            acc1 += rk[hp + 1] * wh[(size_t)(hp + 1) * NH];
            acc2 += rk[hp + 2] * wh[(size_t)(hp + 2) * NH];
            acc3 += rk[hp + 3] * wh[(size_t)(hp + 3) * NH];
        }
        __shared__ float hp_s[8][128];
        hp_s[part][tid & 127] = (acc0 + acc1) + (acc2 + acc3);
        __syncthreads();
        if (tid < 128) {
            float s = ((hp_s[0][tid] + hp_s[1][tid]) + (hp_s[2][tid] + hp_s[3][tid]))
                    + ((hp_s[4][tid] + hp_s[5][tid]) + (hp_s[6][tid] + hp_s[7][tid]));
            g_hpre[k][half * 128 + tid] = bias[half * 128 + tid] + s;
        }
    }
}

// ---------------------------------------------------------------------------
// Main: y[b][k][i] = sum_s x[b][s][i] * (x[b][s] . u[k]),  k = 0..2
// ---------------------------------------------------------------------------
__global__ __launch_bounds__(256) void main_kernel(const float* __restrict__ x)
{
    const int b     = blockIdx.x >> 4;
    const int chunk = blockIdx.x & 15;
    const int warp  = threadIdx.x >> 5;
    const int lane  = threadIdx.x & 31;

    const size_t row0 = (size_t)b * NS + chunk * ROWS_PER_BLOCK + warp * ROWS_PER_WARP;
    const float4* xr = reinterpret_cast<const float4*>(x + row0 * NI) + lane;

    const float4 u0 = reinterpret_cast<const float4*>(g_u[0])[lane];
    const float4 u1 = reinterpret_cast<const float4*>(g_u[1])[lane];
    const float4 u2 = reinterpret_cast<const float4*>(g_u[2])[lane];

    float4 a0 = make_float4(0.f, 0.f, 0.f, 0.f);
    float4 a1 = a0, a2 = a0;

    #pragma unroll 4
    for (int r = 0; r < ROWS_PER_WARP; ++r) {
        const float4 xv = xr[r * 32];
        float d0 = xv.x * u0.x + xv.y * u0.y + xv.z * u0.z + xv.w * u0.w;
        float d1 = xv.x * u1.x + xv.y * u1.y + xv.z * u1.z + xv.w * u1.w;
        float d2 = xv.x * u2.x + xv.y * u2.y + xv.z * u2.z + xv.w * u2.w;
        #pragma unroll
        for (int off = 16; off; off >>= 1) {
            d0 += __shfl_xor_sync(0xffffffffu, d0, off);
            d1 += __shfl_xor_sync(0xffffffffu, d1, off);
            d2 += __shfl_xor_sync(0xffffffffu, d2, off);
        }
        a0.x += d0 * xv.x; a0.y += d0 * xv.y; a0.z += d0 * xv.z; a0.w += d0 * xv.w;
        a1.x += d1 * xv.x; a1.y += d1 * xv.y; a1.z += d1 * xv.z; a1.w += d1 * xv.w;
        a2.x += d2 * xv.x; a2.y += d2 * xv.y; a2.z += d2 * xv.z; a2.w += d2 * xv.w;
    }

    __shared__ float ysw[8][KACT * NI];
    reinterpret_cast<float4*>(&ysw[warp][0 * NI])[lane] = a0;
    reinterpret_cast<float4*>(&ysw[warp][1 * NI])[lane] = a1;
    reinterpret_cast<float4*>(&ysw[warp][2 * NI])[lane] = a2;
    __syncthreads();

    float* yp = g_ypart[b][chunk];
    for (int idx = threadIdx.x; idx < KACT * NI; idx += 256) {
        float s = 0.f;
        #pragma unroll
        for (int w = 0; w < 8; ++w) s += ysw[w][idx];
        yp[idx] = s;
    }
}

// ---------------------------------------------------------------------------
// Epilogue: block per b, 1024 threads, every reduction <= ~2 latency batches.
// ---------------------------------------------------------------------------
__global__ __launch_bounds__(1024) void epilogue_kernel(
    const float* __restrict__ rim, const float* __restrict__ Wv,
    const float* __restrict__ Wih, float* __restrict__ out)
{
    const int b = blockIdx.x;
    const int tid = threadIdx.x;
    __shared__ float ys[KACT * NI];
    __shared__ float attp[2][KACT * NA];
    __shared__ float att[KACT * NA];

    // ---- y: 384 outputs, 16 fully-unrolled loads each (1 batch)
    if (tid < KACT * NI) {
        const float* yp = &g_ypart[b][0][0];
        float s0, s1, s2, s3;
        s0 = yp[0 * (KACT * NI) + tid];
        s1 = yp[1 * (KACT * NI) + tid];
        s2 = yp[2 * (KACT * NI) + tid];
        s3 = yp[3 * (KACT * NI) + tid];
        #pragma unroll
        for (int c = 4; c < CHUNKS; c += 4) {
            s0 += yp[(c + 0) * (KACT * NI) + tid];
            s1 += yp[(c + 1) * (KACT * NI) + tid];
            s2 += yp[(c + 2) * (KACT * NI) + tid];
            s3 += yp[(c + 3) * (KACT * NI) + tid];
        }
        ys[tid] = (s0 + s1) + (s2 + s3);
    }
    __syncthreads();

    // ---- att[k][a] = sum_i Wv[k][i][a]*ys[k][i]; 2-way split over i
    if (tid < 2 * KACT * NA) {
        const int j = tid & (KACT * NA - 1) ? tid % (KACT * NA) : tid % (KACT * NA);
        const int jj   = tid % (KACT * NA);
        const int half = tid / (KACT * NA);     // 0 or 1
        const int k = jj >> 7, a = jj & 127;
        const float* __restrict__ wv = Wv + (size_t)k * NI * NA + (size_t)(half * 64) * NA + a;
        const float* __restrict__ yk = ys + k * NI + half * 64;
        float acc0 = 0.f, acc1 = 0.f, acc2 = 0.f, acc3 = 0.f;
        #pragma unroll
        for (int i = 0; i < 64; i += 4) {
            acc0 += wv[(size_t)(i + 0) * NA] * yk[i + 0];
            acc1 += wv[(size_t)(i + 1) * NA] * yk[i + 1];
            acc2 += wv[(size_t)(i + 2) * NA] * yk[i + 2];
            acc3 += wv[(size_t)(i + 3) * NA] * yk[i + 3];
        }
        attp[half][jj] = (acc0 + acc1) + (acc2 + acc3);
        (void)j;
    }
    __syncthreads();
    if (tid < KACT * NA) att[tid] = attp[0][tid] + attp[1][tid];
    __syncthreads();

    float* ob = out + (size_t)b * NK * NH;

    // ---- cand: 768 outputs, 128-long reduce fully unrolled in chunks of 32
    if (tid < KACT * NH) {
        const int k = tid >> 8, h = tid & 255;
        const float* __restrict__ ak = att + k * NA;
        const float* __restrict__ wih = Wih + h;
        float acc0 = g_hpre[k][h], acc1 = 0.f, acc2 = 0.f, acc3 = 0.f;
        #pragma unroll
        for (int a = 0; a < NA; a += 4) {
            acc0 += ak[a + 0] * wih[(size_t)(a + 0) * NH];
            acc1 += ak[a + 1] * wih[(size_t)(a + 1) * NH];
            acc2 += ak[a + 2] * wih[(size_t)(a + 2) * NH];
            acc3 += ak[a + 3] * wih[(size_t)(a + 3) * NH];
        }
        ob[tid] = tanhf((acc0 + acc1) + (acc2 + acc3));
    }
    // ---- k = 3..7: passthrough rim_hidden (1280 floats)
    for (int j = tid; j < (NK - KACT) * NH; j += 1024) {
        ob[KACT * NH + j] = rim[KACT * NH + j];
    }
}

// ---------------------------------------------------------------------------
extern "C" void kernel_launch(void* const* d_in, const int* in_sizes, int n_in,
                              void* d_out, int out_size)
{
    const float* x    = (const float*)d_in[0];
    const float* rim  = (const float*)d_in[1];
    const float* Wq   = (const float*)d_in[2];
    const float* Wk   = (const float*)d_in[3];
    const float* Wv   = (const float*)d_in[4];
    const float* Wih  = (const float*)d_in[5];
    const float* Whh  = (const float*)d_in[6];
    const float* bias = (const float*)d_in[7];
    float* out = (float*)d_out;

    prologue_kernel<<<KACT + 2 * KACT, 1024>>>(rim, Wq, Wk, Whh, bias);
    main_kernel<<<NB * CHUNKS, 256>>>(x);
    epilogue_kernel<<<NB, 1024>>>(rim, Wv, Wih, out);
}